// round 2
// baseline (speedup 1.0000x reference)
#include <cuda_runtime.h>

#define HH 256
#define WW 256
#define KTOP 10
#define RADIUS 0.015f
#define RR2 (RADIUS * RADIUS)
#define ZFAR 1e10f
#define EPSD 1e-4f
#define NP 20000
#define NTILES 256   // 16x16 tiles of 16x16 pixels

// ---------------- scratch (no allocations allowed) ----------------
__device__ float4 g_proj[NP];          // x_ndc, y_ndc, z (z<=0 => invalid), unused
__device__ int    g_count[NTILES];
__device__ int    g_offset[NTILES];
__device__ int    g_cursor[NTILES];
__device__ float4 g_entries[4 * NP];   // worst case 4 tiles per point

// -------------------------------------------------------------------
__global__ void k_zero_counts() {
    g_count[threadIdx.x] = 0;
}

__device__ __forceinline__ bool tile_range(float xn, float yn,
                                           int& tx0, int& tx1, int& ty0, int& ty1) {
    // pixel w: xs(w) = 1 - (2w+1)/W  (decreasing in w). Coverage needs |xs - xn| < R.
    float wlo = (1.f - (xn + RADIUS)) * (WW * 0.5f) - 0.5f;
    float whi = (1.f - (xn - RADIUS)) * (WW * 0.5f) - 0.5f;
    int wmin = (int)floorf(wlo);
    int wmax = (int)ceilf(whi);
    float hlo = (1.f - (yn + RADIUS)) * (HH * 0.5f) - 0.5f;
    float hhi = (1.f - (yn - RADIUS)) * (HH * 0.5f) - 0.5f;
    int hmin = (int)floorf(hlo);
    int hmax = (int)ceilf(hhi);
    if (wmax < 0 || wmin > WW - 1 || hmax < 0 || hmin > HH - 1) return false;
    wmin = max(wmin, 0); wmax = min(wmax, WW - 1);
    hmin = max(hmin, 0); hmax = min(hmax, HH - 1);
    tx0 = wmin >> 4; tx1 = wmax >> 4;
    ty0 = hmin >> 4; ty1 = hmax >> 4;
    return true;
}

__global__ void k_project_count(const float* __restrict__ pts,
                                const float* __restrict__ Rm,
                                const float* __restrict__ Tv,
                                const float* __restrict__ focal,
                                const float* __restrict__ pp) {
    int p = blockIdx.x * blockDim.x + threadIdx.x;
    if (p >= NP) return;
    float px = pts[3 * p + 0];
    float py = pts[3 * p + 1];
    float pz = pts[3 * p + 2];
    // pc = points @ R + T   (row-vector * matrix): pc_j = sum_i p_i * R[i][j]
    float cx = fmaf(px, Rm[0], fmaf(py, Rm[3], fmaf(pz, Rm[6], Tv[0])));
    float cy = fmaf(px, Rm[1], fmaf(py, Rm[4], fmaf(pz, Rm[7], Tv[1])));
    float cz = fmaf(px, Rm[2], fmaf(py, Rm[5], fmaf(pz, Rm[8], Tv[2])));
    float4 pr;
    if (cz > 0.01f) {
        float iz = 1.0f / cz;
        pr.x = fmaf(focal[0] * cx, iz, pp[0]);
        pr.y = fmaf(focal[1] * cy, iz, pp[1]);
        pr.z = cz;
        pr.w = 0.f;
    } else {
        pr.x = 0.f; pr.y = 0.f; pr.z = -1.f; pr.w = 0.f;
    }
    g_proj[p] = pr;
    if (pr.z > 0.f) {
        int tx0, tx1, ty0, ty1;
        if (tile_range(pr.x, pr.y, tx0, tx1, ty0, ty1)) {
            for (int ty = ty0; ty <= ty1; ty++)
                for (int tx = tx0; tx <= tx1; tx++)
                    atomicAdd(&g_count[ty * 16 + tx], 1);
        }
    }
}

__global__ void k_scan() {
    __shared__ int s[NTILES];
    int t = threadIdx.x;
    int v = g_count[t];
    s[t] = v;
    __syncthreads();
    for (int d = 1; d < NTILES; d <<= 1) {
        int add = (t >= d) ? s[t - d] : 0;
        __syncthreads();
        s[t] += add;
        __syncthreads();
    }
    int excl = s[t] - v;
    g_offset[t] = excl;
    g_cursor[t] = excl;
}

__global__ void k_scatter() {
    int p = blockIdx.x * blockDim.x + threadIdx.x;
    if (p >= NP) return;
    float4 pr = g_proj[p];
    if (pr.z <= 0.f) return;
    int tx0, tx1, ty0, ty1;
    if (!tile_range(pr.x, pr.y, tx0, tx1, ty0, ty1)) return;
    float4 e = make_float4(pr.x, pr.y, pr.z, __int_as_float(p));
    for (int ty = ty0; ty <= ty1; ty++)
        for (int tx = tx0; tx <= tx1; tx++) {
            int pos = atomicAdd(&g_cursor[ty * 16 + tx], 1);
            g_entries[pos] = e;
        }
}

__global__ void k_render(const float* __restrict__ feats, float* __restrict__ out) {
    int tile = blockIdx.x;
    int txi = tile & 15, tyi = tile >> 4;
    int t = threadIdx.x;
    int w = txi * 16 + (t & 15);
    int h = tyi * 16 + (t >> 4);
    float xs = 1.f - (2.f * w + 1.f) * (1.f / WW);
    float ys = 1.f - (2.f * h + 1.f) * (1.f / HH);

    float zk[KTOP], dk[KTOP];
    int ik[KTOP];
#pragma unroll
    for (int k = 0; k < KTOP; k++) { zk[k] = ZFAR; dk[k] = 0.f; ik[k] = 0x7fffffff; }

    int n = g_count[tile];
    int base = g_offset[tile];
    __shared__ float4 sh[256];

    for (int c = 0; c < n; c += 256) {
        int m = min(256, n - c);
        __syncthreads();
        if (t < m) sh[t] = g_entries[base + c + t];
        __syncthreads();
        for (int j = 0; j < m; j++) {
            float4 e = sh[j];
            float dx = xs - e.x;
            float dy = ys - e.y;
            float d2 = fmaf(dx, dx, dy * dy);
            if (d2 < RR2) {
                float zc = e.z, dc = d2;
                int ic = __float_as_int(e.w);
                // skip the swap chain entirely if behind current worst
                bool beats_worst = (zc < zk[KTOP - 1]) ||
                                   (zc == zk[KTOP - 1] && ic < ik[KTOP - 1]);
                if (beats_worst) {
                    // insertion sort, key = (z, idx) lexicographic ascending
#pragma unroll
                    for (int k = 0; k < KTOP; k++) {
                        bool lt = (zc < zk[k]) || (zc == zk[k] && ic < ik[k]);
                        if (lt) {
                            float tz = zk[k]; zk[k] = zc; zc = tz;
                            float td = dk[k]; dk[k] = dc; dc = td;
                            int ti = ik[k]; ik[k] = ic; ic = ti;
                        }
                    }
                }
            }
        }
    }

    // front-to-back composite (matches cumprod ordering of reference)
    float T = 1.f, wsum = 0.f, wz = 0.f;
    float r = 0.f, g = 0.f, b = 0.f;
#pragma unroll
    for (int k = 0; k < KTOP; k++) {
        if (zk[k] < 0.5f * ZFAR) {
            float wgt = 1.f - dk[k] * (1.f / RR2);
            int i = ik[k];
            float fr = feats[3 * i + 0];
            float fg = feats[3 * i + 1];
            float fb = feats[3 * i + 2];
            float cw = wgt * T;
            r = fmaf(cw, fr, r); g = fmaf(cw, fg, g); b = fmaf(cw, fb, b);
            wsum += wgt;
            wz = fmaf(wgt, zk[k], wz);
            T *= (1.f - wgt);
        }
    }
    int pix = h * WW + w;
    out[pix * 3 + 0] = fminf(fmaxf(r, 0.f), 1.f);
    out[pix * 3 + 1] = fminf(fmaxf(g, 0.f), 1.f);
    out[pix * 3 + 2] = fminf(fmaxf(b, 0.f), 1.f);
    out[HH * WW * 3 + pix] = 1.f - T;                    // mask
    out[HH * WW * 4 + pix] = wz / fmaxf(wsum, EPSD);     // depth
}

extern "C" void kernel_launch(void* const* d_in, const int* in_sizes, int n_in,
                              void* d_out, int out_size) {
    const float* points    = (const float*)d_in[0];
    const float* features  = (const float*)d_in[1];
    const float* Rm        = (const float*)d_in[2];
    const float* Tv        = (const float*)d_in[3];
    const float* focal     = (const float*)d_in[4];
    const float* principal = (const float*)d_in[5];
    float* out = (float*)d_out;

    k_zero_counts<<<1, NTILES>>>();
    k_project_count<<<(NP + 255) / 256, 256>>>(points, Rm, Tv, focal, principal);
    k_scan<<<1, NTILES>>>();
    k_scatter<<<(NP + 255) / 256, 256>>>();
    k_render<<<NTILES, 256>>>(features, out);
}

// round 3
// speedup vs baseline: 1.5340x; 1.5340x over previous
#include <cuda_runtime.h>

#define HH 256
#define WW 256
#define KTOP 10
#define RADIUS 0.015f
#define RR2 (RADIUS * RADIUS)
#define ZFAR 1e10f
#define EPSD 1e-4f
#define NP 20000

#define TSH 3                 // log2(tile side) = 8x8 pixel tiles
#define TSIDE 8
#define TGX (WW / TSIDE)      // 32 tiles per dim
#define NTILES (TGX * TGX)    // 1024
#define CAP 256               // entries per tile (expected ~67, >>20 sigma margin)

// ---------------- scratch (no allocations allowed) ----------------
__device__ int    g_count[NTILES];          // zero-initialized; re-zeroed by k_render
__device__ float4 g_bin[NTILES * CAP];      // {x_ndc, y_ndc, z, idx-as-float}

// -------------------------------------------------------------------
// Fused projection + tile binning. One pass, no intermediate buffers.
__global__ void k_bin(const float* __restrict__ pts,
                      const float* __restrict__ Rm,
                      const float* __restrict__ Tv,
                      const float* __restrict__ focal,
                      const float* __restrict__ pp) {
    int p = blockIdx.x * blockDim.x + threadIdx.x;
    if (p >= NP) return;
    float px = pts[3 * p + 0];
    float py = pts[3 * p + 1];
    float pz = pts[3 * p + 2];
    // pc = points @ R + T (row-vector * matrix): pc_j = sum_i p_i * R[i][j]
    float cx = fmaf(px, __ldg(Rm + 0), fmaf(py, __ldg(Rm + 3), fmaf(pz, __ldg(Rm + 6), __ldg(Tv + 0))));
    float cy = fmaf(px, __ldg(Rm + 1), fmaf(py, __ldg(Rm + 4), fmaf(pz, __ldg(Rm + 7), __ldg(Tv + 1))));
    float cz = fmaf(px, __ldg(Rm + 2), fmaf(py, __ldg(Rm + 5), fmaf(pz, __ldg(Rm + 8), __ldg(Tv + 2))));
    if (cz <= 0.01f) return;
    float iz = 1.0f / cz;
    float xn = fmaf(__ldg(focal + 0) * cx, iz, __ldg(pp + 0));
    float yn = fmaf(__ldg(focal + 1) * cy, iz, __ldg(pp + 1));

    // pixel w: xs(w) = 1 - (2w+1)/W (decreasing in w). Coverage needs |xs - xn| < R.
    float wlo = (1.f - (xn + RADIUS)) * (WW * 0.5f) - 0.5f;
    float whi = (1.f - (xn - RADIUS)) * (WW * 0.5f) - 0.5f;
    int wmin = (int)floorf(wlo);
    int wmax = (int)ceilf(whi);
    float hlo = (1.f - (yn + RADIUS)) * (HH * 0.5f) - 0.5f;
    float hhi = (1.f - (yn - RADIUS)) * (HH * 0.5f) - 0.5f;
    int hmin = (int)floorf(hlo);
    int hmax = (int)ceilf(hhi);
    if (wmax < 0 || wmin > WW - 1 || hmax < 0 || hmin > HH - 1) return;
    wmin = max(wmin, 0); wmax = min(wmax, WW - 1);
    hmin = max(hmin, 0); hmax = min(hmax, HH - 1);
    int tx0 = wmin >> TSH, tx1 = wmax >> TSH;
    int ty0 = hmin >> TSH, ty1 = hmax >> TSH;

    float4 e = make_float4(xn, yn, cz, __int_as_float(p));
    for (int ty = ty0; ty <= ty1; ty++)
        for (int tx = tx0; tx <= tx1; tx++) {
            int tile = ty * TGX + tx;
            int pos = atomicAdd(&g_count[tile], 1);
            if (pos < CAP) g_bin[tile * CAP + pos] = e;
        }
}

// -------------------------------------------------------------------
// One 64-thread block per 8x8 tile; one thread per pixel.
__global__ void __launch_bounds__(64) k_render(const float* __restrict__ feats,
                                               float* __restrict__ out) {
    int tile = blockIdx.x;
    int txi = tile & (TGX - 1), tyi = tile >> 5;
    int t = threadIdx.x;
    int w = txi * TSIDE + (t & (TSIDE - 1));
    int h = tyi * TSIDE + (t >> TSH);
    float xs = 1.f - (2.f * w + 1.f) * (1.f / WW);
    float ys = 1.f - (2.f * h + 1.f) * (1.f / HH);

    float zk[KTOP], dk[KTOP];
    int ik[KTOP];
#pragma unroll
    for (int k = 0; k < KTOP; k++) { zk[k] = ZFAR; dk[k] = 0.f; ik[k] = 0x7fffffff; }

    int n = min(g_count[tile], CAP);
    const float4* bin = g_bin + tile * CAP;
    __shared__ float4 sh[CAP];
    // stage this tile's list into smem (typically one pass, n~67)
    for (int j = t; j < n; j += 64) sh[j] = bin[j];
    __syncthreads();
    if (t == 0) g_count[tile] = 0;   // re-arm for next graph replay

#pragma unroll 4
    for (int j = 0; j < n; j++) {
        float4 e = sh[j];
        float dx = xs - e.x;
        float dy = ys - e.y;
        float d2 = fmaf(dx, dx, dy * dy);
        if (d2 < RR2) {
            float zc = e.z, dc = d2;
            int ic = __float_as_int(e.w);
            // skip the 10-deep swap chain if behind current worst
            bool beats_worst = (zc < zk[KTOP - 1]) ||
                               (zc == zk[KTOP - 1] && ic < ik[KTOP - 1]);
            if (beats_worst) {
                // insertion sort, key = (z, idx) lexicographic ascending
                // (matches top_k(-zbuf) incl. lowest-index tie-break)
#pragma unroll
                for (int k = 0; k < KTOP; k++) {
                    bool lt = (zc < zk[k]) || (zc == zk[k] && ic < ik[k]);
                    if (lt) {
                        float tz = zk[k]; zk[k] = zc; zc = tz;
                        float td = dk[k]; dk[k] = dc; dc = td;
                        int ti = ik[k]; ik[k] = ic; ic = ti;
                    }
                }
            }
        }
    }

    // front-to-back composite (matches cumprod ordering of reference)
    float T = 1.f, wsum = 0.f, wz = 0.f;
    float r = 0.f, g = 0.f, b = 0.f;
#pragma unroll
    for (int k = 0; k < KTOP; k++) {
        if (zk[k] < 0.5f * ZFAR) {
            float wgt = 1.f - dk[k] * (1.f / RR2);
            int i = ik[k];
            float fr = feats[3 * i + 0];
            float fg = feats[3 * i + 1];
            float fb = feats[3 * i + 2];
            float cw = wgt * T;
            r = fmaf(cw, fr, r); g = fmaf(cw, fg, g); b = fmaf(cw, fb, b);
            wsum += wgt;
            wz = fmaf(wgt, zk[k], wz);
            T *= (1.f - wgt);
        }
    }
    int pix = h * WW + w;
    out[pix * 3 + 0] = fminf(fmaxf(r, 0.f), 1.f);
    out[pix * 3 + 1] = fminf(fmaxf(g, 0.f), 1.f);
    out[pix * 3 + 2] = fminf(fmaxf(b, 0.f), 1.f);
    out[HH * WW * 3 + pix] = 1.f - T;                    // mask
    out[HH * WW * 4 + pix] = wz / fmaxf(wsum, EPSD);     // depth
}

extern "C" void kernel_launch(void* const* d_in, const int* in_sizes, int n_in,
                              void* d_out, int out_size) {
    const float* points    = (const float*)d_in[0];
    const float* features  = (const float*)d_in[1];
    const float* Rm        = (const float*)d_in[2];
    const float* Tv        = (const float*)d_in[3];
    const float* focal     = (const float*)d_in[4];
    const float* principal = (const float*)d_in[5];
    float* out = (float*)d_out;

    k_bin<<<(NP + 255) / 256, 256>>>(points, Rm, Tv, focal, principal);
    k_render<<<NTILES, 64>>>(features, out);
}

// round 5
// speedup vs baseline: 2.3830x; 1.5534x over previous
#include <cuda_runtime.h>

#define HH 256
#define WW 256
#define KTOP 10
#define RADIUS 0.015f
#define RR2 (RADIUS * RADIUS)
#define EPSD 1e-4f
#define NP 20000

#define TSH 3                 // log2(tile side): 8x8 pixel tiles
#define TSIDE 8
#define TGX (WW / TSIDE)      // 32 tiles per dim
#define NTILES (TGX * TGX)    // 1024
#define CAP 256               // entries per tile (expected ~67)

typedef unsigned long long u64;
typedef unsigned int u32;

// ---------------- scratch (no allocations allowed) ----------------
__device__ int    g_count[NTILES];          // zero-init; re-zeroed by k_render
__device__ float4 g_bin[NTILES * CAP];      // {x_ndc, y_ndc, z, idx-as-float}

// -------------------------------------------------------------------
// Fused projection + tile binning.
__global__ void k_bin(const float* __restrict__ pts,
                      const float* __restrict__ Rm,
                      const float* __restrict__ Tv,
                      const float* __restrict__ focal,
                      const float* __restrict__ pp) {
    int p = blockIdx.x * blockDim.x + threadIdx.x;
    if (p >= NP) return;
    float px = pts[3 * p + 0];
    float py = pts[3 * p + 1];
    float pz = pts[3 * p + 2];
    // pc = points @ R + T (row-vector * matrix): pc_j = sum_i p_i * R[i][j]
    float cx = fmaf(px, __ldg(Rm + 0), fmaf(py, __ldg(Rm + 3), fmaf(pz, __ldg(Rm + 6), __ldg(Tv + 0))));
    float cy = fmaf(px, __ldg(Rm + 1), fmaf(py, __ldg(Rm + 4), fmaf(pz, __ldg(Rm + 7), __ldg(Tv + 1))));
    float cz = fmaf(px, __ldg(Rm + 2), fmaf(py, __ldg(Rm + 5), fmaf(pz, __ldg(Rm + 8), __ldg(Tv + 2))));
    if (cz <= 0.01f) return;
    float iz = 1.0f / cz;
    float xn = fmaf(__ldg(focal + 0) * cx, iz, __ldg(pp + 0));
    float yn = fmaf(__ldg(focal + 1) * cy, iz, __ldg(pp + 1));

    // pixel w: xs(w) = 1 - (2w+1)/W (decreasing in w). Coverage: |xs - xn| < R.
    float wlo = (1.f - (xn + RADIUS)) * (WW * 0.5f) - 0.5f;
    float whi = (1.f - (xn - RADIUS)) * (WW * 0.5f) - 0.5f;
    int wmin = (int)floorf(wlo);
    int wmax = (int)ceilf(whi);
    float hlo = (1.f - (yn + RADIUS)) * (HH * 0.5f) - 0.5f;
    float hhi = (1.f - (yn - RADIUS)) * (HH * 0.5f) - 0.5f;
    int hmin = (int)floorf(hlo);
    int hmax = (int)ceilf(hhi);
    if (wmax < 0 || wmin > WW - 1 || hmax < 0 || hmin > HH - 1) return;
    wmin = max(wmin, 0); wmax = min(wmax, WW - 1);
    hmin = max(hmin, 0); hmax = min(hmax, HH - 1);
    int tx0 = wmin >> TSH, tx1 = wmax >> TSH;
    int ty0 = hmin >> TSH, ty1 = hmax >> TSH;

    float4 e = make_float4(xn, yn, cz, __int_as_float(p));
    for (int ty = ty0; ty <= ty1; ty++)
        for (int tx = tx0; tx <= tx1; tx++) {
            int tile = ty * TGX + tx;
            int pos = atomicAdd(&g_count[tile], 1);
            if (pos < CAP) g_bin[tile * CAP + pos] = e;
        }
}

// -------------------------------------------------------------------
// One 64-thread block per 8x8 tile; one thread per pixel.
// Sort tile entries by (z, idx) once, permute into order, then stream composite.
__global__ void __launch_bounds__(64) k_render(const float* __restrict__ feats,
                                               float* __restrict__ out) {
    int tile = blockIdx.x;
    int txi = tile & (TGX - 1), tyi = tile >> 5;
    int t = threadIdx.x;
    int w = txi * TSIDE + (t & (TSIDE - 1));
    int h = tyi * TSIDE + (t >> TSH);
    float xs = 1.f - (2.f * w + 1.f) * (1.f / WW);
    float ys = 1.f - (2.f * h + 1.f) * (1.f / HH);

    int n = min(g_count[tile], CAP);
    if (t == 0 && n) g_count[tile] = 0;   // re-arm for next graph replay
    const float4* bin = g_bin + tile * CAP;

    __shared__ float4 sh[CAP];    // entry {x,y,z,idxf} (load order)
    __shared__ float4 sf[CAP];    // entry feature rgb  (load order)
    __shared__ u64    skey[CAP];  // (z_bits<<32)|idx — ascending == (z,idx) lexicographic
    __shared__ int    sid[CAP];   // permutation after sort
    __shared__ float4 she[CAP];   // entries in sorted order
    __shared__ float4 sfe[CAP];   // features in sorted order

    unsigned m = 1;               // pad to power of two for bitonic
    while (m < (unsigned)n) m <<= 1;

    for (unsigned j = t; j < m; j += 64) {
        if (j < (unsigned)n) {
            float4 e = bin[j];
            sh[j] = e;
            int idx = __float_as_int(e.w);
            skey[j] = ((u64)__float_as_uint(e.z) << 32) | (u32)idx;
            const float* f = feats + 3 * idx;
            sf[j] = make_float4(f[0], f[1], f[2], 0.f);
        } else {
            skey[j] = ~0ull;
        }
        sid[j] = (int)j;
    }
    __syncthreads();

    // bitonic sort of (skey, sid), ascending
    for (unsigned ksz = 2; ksz <= m; ksz <<= 1) {
        for (unsigned jsz = ksz >> 1; jsz > 0; jsz >>= 1) {
            for (unsigned i = t; i < m; i += 64) {
                unsigned ixj = i ^ jsz;
                if (ixj > i) {
                    bool up = ((i & ksz) == 0);
                    u64 a = skey[i], b2 = skey[ixj];
                    if (up ? (a > b2) : (a < b2)) {
                        skey[i] = b2; skey[ixj] = a;
                        int tmp = sid[i]; sid[i] = sid[ixj]; sid[ixj] = tmp;
                    }
                }
            }
            __syncthreads();
        }
    }

    // permute entries/features into sorted order so the hot loop is sequential
    for (int j = t; j < n; j += 64) {
        int id = sid[j];
        she[j] = sh[id];
        sfe[j] = sf[id];
    }
    __syncthreads();

    // streaming front-to-back composite over z-sorted entries.
    // first KTOP hits are exactly top_k(-zbuf) incl. lowest-index tie-break.
    int cnt = 0;
    float T = 1.f, wsum = 0.f, wz = 0.f;
    float r = 0.f, g = 0.f, b = 0.f;
#pragma unroll 4
    for (int j = 0; j < n; j++) {
        float4 e = she[j];
        float dx = xs - e.x;
        float dy = ys - e.y;
        float d2 = fmaf(dx, dx, dy * dy);
        if (d2 < RR2 && cnt < KTOP) {
            float wgt = 1.f - d2 * (1.f / RR2);
            float4 f = sfe[j];
            float cw = wgt * T;
            r = fmaf(cw, f.x, r);
            g = fmaf(cw, f.y, g);
            b = fmaf(cw, f.z, b);
            wsum += wgt;
            wz = fmaf(wgt, e.z, wz);
            T *= (1.f - wgt);
            cnt++;
        }
    }

    int pix = h * WW + w;
    out[pix * 3 + 0] = fminf(fmaxf(r, 0.f), 1.f);
    out[pix * 3 + 1] = fminf(fmaxf(g, 0.f), 1.f);
    out[pix * 3 + 2] = fminf(fmaxf(b, 0.f), 1.f);
    out[HH * WW * 3 + pix] = 1.f - T;                    // mask
    out[HH * WW * 4 + pix] = wz / fmaxf(wsum, EPSD);     // depth
}

extern "C" void kernel_launch(void* const* d_in, const int* in_sizes, int n_in,
                              void* d_out, int out_size) {
    const float* points    = (const float*)d_in[0];
    const float* features  = (const float*)d_in[1];
    const float* Rm        = (const float*)d_in[2];
    const float* Tv        = (const float*)d_in[3];
    const float* focal     = (const float*)d_in[4];
    const float* principal = (const float*)d_in[5];
    float* out = (float*)d_out;

    k_bin<<<(NP + 127) / 128, 128>>>(points, Rm, Tv, focal, principal);
    k_render<<<NTILES, 64>>>(features, out);
}